// round 12
// baseline (speedup 1.0000x reference)
#include <cuda_runtime.h>
#include <math.h>

#define Bn 8
#define Hn 256
#define Wn 256
#define NPIX (Bn*Hn*Wn)       // 524288
#define INF_F 1e10f
#define RW 3                  // window radius; accept bound (RW+1)^2 = 16
#define RW_BOUND 16
#define SR 4                  // strip rows per block
#define MR (SR + 2*RW)        // 10 halo rows
#define SPB (Hn/SR)           // 64 strips per batch
#define NBLK (Bn * SPB)       // 512 blocks

// Per-block partials (disjoint coverage -> no atomics on data, deterministic)
__device__ float d_spt[NBLK];
__device__ float d_sp2[NBLK];
__device__ float d_st [NBLK];
__device__ float d_bnd[NBLK];
__device__ unsigned d_cnt = 0;   // completion counter (reset by last block)

// Unclamped window distance from offset-0 (bit 15) to nearest set bit.
// clz(0)=32 -> d=32 -> d^2=1024 (fits halfword; triggers fallback if min).
__device__ __forceinline__ unsigned win_dist(unsigned v) {
    int dl = __clz(v << 16);             // offset -d -> bit 31-d
    int dr = __clz(__brev(v >> 15));     // offset +d -> bit d -> reversed
    return (unsigned)min(dl, dr);
}

// Exact global fallback (bitwise-matches reference min-plus; never taken for
// benign inputs, preserves worst-case exactness).
__device__ __noinline__ float fb_min(const float* __restrict__ timg,
                                     int i, int w, bool want_one) {
    float m = 3.0e38f;
    for (int j = 0; j < Hn; j++) {
        int best = 1 << 20;
        for (int c = 0; c < Wn; c++) {
            float tv = timg[j * Wn + c];
            bool hit = want_one ? (tv > 0.5f) : (tv <= 0.5f);
            if (hit) best = min(best, abs(w - c));
        }
        float g = (best < Wn) ? (float)(best * best) : INF_F;
        float dj = (float)(i - j);
        m = fminf(m, fmaf(dj, dj, g));
    }
    return m;
}

__global__ void __launch_bounds__(256) fused_kernel(
        const float* __restrict__ pred,
        const float* __restrict__ target,
        const int* __restrict__ flg,
        float* __restrict__ out) {
    __shared__ float rsf[4][8];
    __shared__ unsigned is_last_sh;

    int tid  = threadIdx.x;
    int lane = tid & 31, wwp = tid >> 5;
    int b    = blockIdx.x >> 6;              // batch
    int i0   = (blockIdx.x & 63) * SR;       // strip start row
    int j0   = i0 - RW;
    const float* timg = target + b * (Hn * Wn);
    int fl = flg[0];

    int w0 = wwp * 32;                       // warp's column base
    int w  = w0 + lane;                      // this thread's column
    bool edge = (i0 == 0) || (i0 + SR + RW > Hn);   // strips 0 and 63 only

    // prefetch pred for this thread's column
    const float* prow = pred + (b * Hn + i0) * Wn + w;
    float pv[SR];
    #pragma unroll
    for (int k = 0; k < SR; k++)
        pv[k] = prow[k * Wn];

    // loop-invariant window-validity mask (for the in-EDT polarity)
    int bb = lane;
    int sh = (bb + 17) & 31;
    bool hiSel = (bb >= 15);
    unsigned vmA = __funnelshift_r((wwp >= 1) ? 0xffffffffu : 0u, 0xffffffffu, sh);
    unsigned vmB = __funnelshift_r(0xffffffffu, (wwp <= 6) ? 0xffffffffu : 0u, sh);
    unsigned vm  = hiSel ? vmB : vmA;

    // --- per-warp autonomous: masks via 3 ballots/row, g in registers.
    // No smem, no cross-warp dependency, no barrier until final reduce.
    unsigned g[MR];
    const float* trp = timg + j0 * Wn + w0 + lane;
    if (!edge) {
        #pragma unroll
        for (int r = 0; r < MR; r++) {
            const float* rp = trp + r * Wn;
            unsigned lo = 0u, hi = 0u;
            if (wwp >= 1) lo = __ballot_sync(0xffffffffu, rp[-32] > 0.5f);
            unsigned mid =  __ballot_sync(0xffffffffu, rp[0]   > 0.5f);
            if (wwp <= 6) hi = __ballot_sync(0xffffffffu, rp[32]  > 0.5f);
            unsigned va = __funnelshift_r(lo, mid, sh);
            unsigned vb = __funnelshift_r(mid, hi, sh);
            unsigned v  = hiSel ? vb : va;
            unsigned center = (v >> 15) & 1u;
            unsigned selv = center ? ((~v) & vm) : v;
            unsigned d  = win_dist(selv);
            unsigned d2 = d * d;
            g[r] = center ? (d2 << 16) : d2;
        }
    } else {
        #pragma unroll
        for (int r = 0; r < MR; r++) {
            int j = j0 + r;
            bool okr = (unsigned)j < (unsigned)Hn;
            const float* rp = trp + r * Wn;
            unsigned lo = 0u, hi = 0u;
            if (wwp >= 1) lo = __ballot_sync(0xffffffffu, okr && rp[-32] > 0.5f);
            unsigned mid =  __ballot_sync(0xffffffffu, okr && rp[0]   > 0.5f);
            if (wwp <= 6) hi = __ballot_sync(0xffffffffu, okr && rp[32]  > 0.5f);
            if (okr) {
                unsigned va = __funnelshift_r(lo, mid, sh);
                unsigned vb = __funnelshift_r(mid, hi, sh);
                unsigned v  = hiSel ? vb : va;
                unsigned center = (v >> 15) & 1u;
                unsigned selv = center ? ((~v) & vm) : v;
                unsigned d  = win_dist(selv);
                unsigned d2 = d * d;
                g[r] = center ? (d2 << 16) : d2;
            } else {
                g[r] = 49u | (49u << 16);    // >= 49: never accepted
            }
        }
    }

    // --- windowed column pass; min(mo,mi)==0 so s=mo+mi drives sqrt + bad test
    int mo[SR], mi[SR], s_[SR], smax = 0;
    #pragma unroll
    for (int k = 0; k < SR; k++) {
        unsigned m = g[k] + 0x00090009u;            // q = 9
        m = __vminu2(m, g[k + 1] + 0x00040004u);    // q = 4
        m = __vminu2(m, g[k + 2] + 0x00010001u);    // q = 1
        m = __vminu2(m, g[k + 3]);                  // q = 0 (center)
        m = __vminu2(m, g[k + 4] + 0x00010001u);
        m = __vminu2(m, g[k + 5] + 0x00040004u);
        m = __vminu2(m, g[k + 6] + 0x00090009u);
        mo[k] = (int)(m & 0xffffu);
        mi[k] = (int)(m >> 16);
        s_[k] = mo[k] + mi[k];
        smax = max(smax, s_[k]);
    }

    float dist[SR];
    #pragma unroll
    for (int k = 0; k < SR; k++)
        dist[k] = sqrtf((float)s_[k]);

    if (smax > RW_BOUND) {   // window min <= 16 is provably exact; rare rescue
        #pragma unroll
        for (int k = 0; k < SR; k++) {
            float fmo = (mo[k] <= RW_BOUND) ? (float)mo[k] : fb_min(timg, i0 + k, w, true);
            float fmi = (mi[k] <= RW_BOUND) ? (float)mi[k] : fb_min(timg, i0 + k, w, false);
            dist[k] = sqrtf(fmo) + sqrtf(fmi);
        }
    }

    // --- dice + boundary accumulation (fp32); tb == (mo == 0)
    float spt = 0.f, sp2 = 0.f, stt = 0.f, bsum = 0.f;
    #pragma unroll
    for (int k = 0; k < SR; k++) {
        float p = pv[k];
        if (fl) {   // sigmoid(x) = 0.5 + 0.5*tanh(x/2)
            float th;
            asm("tanh.approx.f32 %0, %1;" : "=f"(th) : "f"(p * 0.5f));
            p = fmaf(th, 0.5f, 0.5f);
        }
        float tb = (mo[k] == 0) ? 1.0f : 0.0f;
        spt  += p * tb;
        sp2  += p * p;
        stt  += tb;
        bsum += p * dist[k];
    }

    // --- warp reduce, then single cross-warp merge (the only barrier)
    #pragma unroll
    for (int o = 16; o; o >>= 1) {
        spt  += __shfl_down_sync(0xffffffffu, spt,  o);
        sp2  += __shfl_down_sync(0xffffffffu, sp2,  o);
        stt  += __shfl_down_sync(0xffffffffu, stt,  o);
        bsum += __shfl_down_sync(0xffffffffu, bsum, o);
    }
    if (lane == 0) { rsf[0][wwp] = spt; rsf[1][wwp] = sp2; rsf[2][wwp] = stt; rsf[3][wwp] = bsum; }
    __syncthreads();

    if (tid == 0) {
        float A = 0.f, Bv = 0.f, C = 0.f, D = 0.f;
        #pragma unroll
        for (int q = 0; q < 8; q++) { A += rsf[0][q]; Bv += rsf[1][q]; C += rsf[2][q]; D += rsf[3][q]; }
        d_spt[blockIdx.x] = A; d_sp2[blockIdx.x] = Bv; d_st[blockIdx.x] = C;
        d_bnd[blockIdx.x] = D;
        __threadfence();
        unsigned prev = atomicAdd(&d_cnt, 1u);
        is_last_sh = (prev == NBLK - 1) ? 1u : 0u;
    }
    __syncthreads();

    // --- last block finalizes (fp64 cross-block combine)
    if (is_last_sh) {
        __shared__ double dsh[8], bsh[8];
        // dice: warp wwp reduces batch wwp's 64 strip-partials (2 per lane)
        int blk = wwp * SPB + lane;
        double a  = (double)__ldcg(&d_spt[blk]) + (double)__ldcg(&d_spt[blk + 32]);
        double bv = (double)__ldcg(&d_sp2[blk]) + (double)__ldcg(&d_sp2[blk + 32]);
        double c  = (double)__ldcg(&d_st [blk]) + (double)__ldcg(&d_st [blk + 32]);
        #pragma unroll
        for (int o = 16; o; o >>= 1) {
            a  += __shfl_down_sync(0xffffffffu, a,  o);
            bv += __shfl_down_sync(0xffffffffu, bv, o);
            c  += __shfl_down_sync(0xffffffffu, c,  o);
        }
        if (lane == 0) dsh[wwp] = 1.0 - (2.0 * a + 1e-6) / (bv + c + 1e-6);

        // boundary: 512 partials across 256 threads (2 each)
        double bd = (double)__ldcg(&d_bnd[tid]) + (double)__ldcg(&d_bnd[tid + 256]);
        #pragma unroll
        for (int o = 16; o; o >>= 1)
            bd += __shfl_down_sync(0xffffffffu, bd, o);
        if (lane == 0) bsh[wwp] = bd;
        __syncthreads();

        if (tid == 0) {
            double d = 0.0, bbv = 0.0;
            #pragma unroll
            for (int q = 0; q < 8; q++) { d += dsh[q]; bbv += bsh[q]; }
            out[0] = (float)(d * (1.0 / (double)Bn) + bbv * (1.0 / (double)NPIX));
            d_cnt = 0;   // reset for next graph replay (deterministic)
        }
    }
}

extern "C" void kernel_launch(void* const* d_in, const int* in_sizes, int n_in,
                              void* d_out, int out_size) {
    const float* pred   = (const float*)d_in[0];
    const float* target = (const float*)d_in[1];
    const int*   flg    = (const int*)d_in[2];
    float* out = (float*)d_out;

    fused_kernel<<<NBLK, 256>>>(pred, target, flg, out);
}

// round 13
// speedup vs baseline: 1.4257x; 1.4257x over previous
#include <cuda_runtime.h>
#include <math.h>

#define Bn 8
#define Hn 256
#define Wn 256
#define NPIX (Bn*Hn*Wn)       // 524288
#define INF_F 1e10f
#define RW 3                  // window radius; accept bound (RW+1)^2 = 16
#define RW_BOUND 16
#define SR 8                  // strip rows per block
#define MR (SR + 2*RW)        // 14 halo rows per block
#define SPB (Hn/SR)           // 32 strips per batch
#define NBLK (Bn * SPB)       // 256 blocks

// Packed per-block partials {spt, sp2, st, bnd}; disjoint coverage -> deterministic
__device__ float4 d_part[NBLK];
__device__ unsigned d_cnt = 0;   // completion counter (reset by last block)

// Unclamped window distance from offset-0 (bit 15) to nearest set bit.
// clz(0)=32 -> d=32 -> d^2=1024 (fits halfword; triggers fallback if min).
__device__ __forceinline__ unsigned win_dist(unsigned v) {
    int dl = __clz(v << 16);             // offset -d -> bit 31-d
    int dr = __clz(__brev(v >> 15));     // offset +d -> bit d -> reversed
    return (unsigned)min(dl, dr);
}

// Exact global fallback (bitwise-matches reference min-plus; never taken for
// benign inputs, preserves worst-case exactness).
__device__ __noinline__ float fb_min(const float* __restrict__ timg,
                                     int i, int w, bool want_one) {
    float m = 3.0e38f;
    for (int j = 0; j < Hn; j++) {
        int best = 1 << 20;
        for (int c = 0; c < Wn; c++) {
            float tv = timg[j * Wn + c];
            bool hit = want_one ? (tv > 0.5f) : (tv <= 0.5f);
            if (hit) best = min(best, abs(w - c));
        }
        float g = (best < Wn) ? (float)(best * best) : INF_F;
        float dj = (float)(i - j);
        m = fminf(m, fmaf(dj, dj, g));
    }
    return m;
}

__global__ void __launch_bounds__(256) fused_kernel(
        const float* __restrict__ pred,
        const float* __restrict__ target,
        const int* __restrict__ flg,
        float* __restrict__ out) {
    __shared__ unsigned mskT[10][16];    // [seg -1..8][row 0..13], stride 16
    __shared__ float sq[64];             // sqrt LUT (exact sqrtf values)
    __shared__ float rsf[4][8];
    __shared__ unsigned is_last_sh;

    int tid  = threadIdx.x;
    int lane = tid & 31, wwp = tid >> 5;
    int b    = blockIdx.x >> 5;              // batch
    int i0   = (blockIdx.x & 31) * SR;       // strip start row
    int j0   = i0 - RW;
    const float* timg = target + b * (Hn * Wn);
    int fl = flg[0];

    // ---- pred loads FIRST: 8 independent LDGs in flight (max MLP)
    int w = tid;
    const float* prow = pred + (b * Hn + i0) * Wn + w;
    float pv[SR];
    #pragma unroll
    for (int k = 0; k < SR; k++)
        pv[k] = prow[k * Wn];

    // init: sqrt LUT + guard segments (global seg -1 and 8)
    if (tid < 64) {
        sq[tid] = sqrtf((float)tid);
    } else if (tid < 64 + 2 * MR) {
        int q = tid - 64;
        mskT[(q < MR) ? 0 : 9][(q < MR) ? q : (q - MR)] = 0u;
    }

    bool edge = (i0 == 0) || (i0 + SR + RW > Hn);   // strips 0 and 31 only

    // --- target bitmasks, one warp per halo row; FFMA packing (t is 0/1 exact).
    // Lane covers cols 8l..8l+7; 4-lane groups merge into one 32-col segment.
    #pragma unroll
    for (int rr = 0; rr < 2; rr++) {
        int r = wwp + rr * 8;
        int j = j0 + r;
        bool okr = (rr == 0 || wwp < MR - 8) &&
                   (!edge || (unsigned)j < (unsigned)Hn);
        if (okr) {
            const float4* tp = (const float4*)(timg + j * Wn) + lane * 2;
            float4 a = tp[0], c = tp[1];
            float s = a.x;
            s = fmaf(a.y,   2.f, s); s = fmaf(a.z,   4.f, s); s = fmaf(a.w,   8.f, s);
            s = fmaf(c.x,  16.f, s); s = fmaf(c.y,  32.f, s); s = fmaf(c.z,  64.f, s);
            s = fmaf(c.w, 128.f, s);
            unsigned v = ((unsigned)(int)s) << ((lane & 3) * 8);
            v |= __shfl_down_sync(0xffffffffu, v, 1, 4);
            v |= __shfl_down_sync(0xffffffffu, v, 2, 4);
            if ((lane & 3) == 0) mskT[(lane >> 2) + 1][r] = v;
        }
    }
    __syncthreads();

    // --- per-column row distances, packed dx^2 | dy^2<<16 (registers).
    int ww = w >> 5, bb = w & 31;
    int sh = (bb + 17) & 31;                 // uniform funnel shift amount
    bool hiSel = (bb >= 15);
    unsigned vmA = __funnelshift_r((ww >= 1) ? 0xffffffffu : 0u, 0xffffffffu, sh);
    unsigned vmB = __funnelshift_r(0xffffffffu, (ww <= 6) ? 0xffffffffu : 0u, sh);
    unsigned vm  = hiSel ? vmB : vmA;        // loop-invariant valid-column mask

    const unsigned* bp = &mskT[ww][0];       // segs ww-1, ww, ww+1 at +0,+16,+32
    unsigned g[MR];
    if (!edge) {
        #pragma unroll
        for (int r = 0; r < MR; r++) {
            unsigned lo = bp[r], mw = bp[16 + r], hi = bp[32 + r];
            unsigned va = __funnelshift_r(lo, mw, sh);
            unsigned vb = __funnelshift_r(mw, hi, sh);
            unsigned v  = hiSel ? vb : va;
            unsigned center = (v >> 15) & 1u;
            unsigned selv = center ? ((~v) & vm) : v;
            unsigned d  = win_dist(selv);
            unsigned d2 = d * d;
            g[r] = center ? (d2 << 16) : d2;
        }
    } else {
        #pragma unroll
        for (int r = 0; r < MR; r++) {
            int j = j0 + r;
            if ((unsigned)j < (unsigned)Hn) {
                unsigned lo = bp[r], mw = bp[16 + r], hi = bp[32 + r];
                unsigned va = __funnelshift_r(lo, mw, sh);
                unsigned vb = __funnelshift_r(mw, hi, sh);
                unsigned v  = hiSel ? vb : va;
                unsigned center = (v >> 15) & 1u;
                unsigned selv = center ? ((~v) & vm) : v;
                unsigned d  = win_dist(selv);
                unsigned d2 = d * d;
                g[r] = center ? (d2 << 16) : d2;
            } else {
                g[r] = 49u | (49u << 16);    // >= 49: never accepted
            }
        }
    }

    // --- windowed column pass; min(mo,mi)==0 so s=mo+mi drives sqrt + bad test
    int mo[SR], mi[SR], s_[SR], smax = 0;
    #pragma unroll
    for (int k = 0; k < SR; k++) {
        unsigned m = g[k] + 0x00090009u;            // q = 9
        m = __vminu2(m, g[k + 1] + 0x00040004u);    // q = 4
        m = __vminu2(m, g[k + 2] + 0x00010001u);    // q = 1
        m = __vminu2(m, g[k + 3]);                  // q = 0 (center)
        m = __vminu2(m, g[k + 4] + 0x00010001u);
        m = __vminu2(m, g[k + 5] + 0x00040004u);
        m = __vminu2(m, g[k + 6] + 0x00090009u);
        mo[k] = (int)(m & 0xffffu);
        mi[k] = (int)(m >> 16);
        s_[k] = mo[k] + mi[k];
        smax = max(smax, s_[k]);
    }

    float dist[SR];
    #pragma unroll
    for (int k = 0; k < SR; k++)
        dist[k] = sq[min(s_[k], 63)];

    if (smax > RW_BOUND) {   // window min <= 16 is provably exact; rare rescue
        #pragma unroll
        for (int k = 0; k < SR; k++) {
            float fmo = (mo[k] <= RW_BOUND) ? (float)mo[k] : fb_min(timg, i0 + k, w, true);
            float fmi = (mi[k] <= RW_BOUND) ? (float)mi[k] : fb_min(timg, i0 + k, w, false);
            dist[k] = sqrtf(fmo) + sqrtf(fmi);
        }
    }

    // --- dice + boundary accumulation (fp32); tb == (mo == 0)
    float spt = 0.f, sp2 = 0.f, stt = 0.f, bsum = 0.f;
    #pragma unroll
    for (int k = 0; k < SR; k++) {
        float p = pv[k];
        if (fl) {   // sigmoid(x) = 0.5 + 0.5*tanh(x/2)
            float th;
            asm("tanh.approx.f32 %0, %1;" : "=f"(th) : "f"(p * 0.5f));
            p = fmaf(th, 0.5f, 0.5f);
        }
        float tb = (mo[k] == 0) ? 1.0f : 0.0f;
        spt  += p * tb;
        sp2  += p * p;
        stt  += tb;
        bsum += p * dist[k];
    }

    // --- block reduction (fp32)
    #pragma unroll
    for (int o = 16; o; o >>= 1) {
        spt  += __shfl_down_sync(0xffffffffu, spt,  o);
        sp2  += __shfl_down_sync(0xffffffffu, sp2,  o);
        stt  += __shfl_down_sync(0xffffffffu, stt,  o);
        bsum += __shfl_down_sync(0xffffffffu, bsum, o);
    }
    if (lane == 0) { rsf[0][wwp] = spt; rsf[1][wwp] = sp2; rsf[2][wwp] = stt; rsf[3][wwp] = bsum; }
    __syncthreads();

    if (tid == 0) {
        float A = 0.f, Bv = 0.f, C = 0.f, D = 0.f;
        #pragma unroll
        for (int q = 0; q < 8; q++) { A += rsf[0][q]; Bv += rsf[1][q]; C += rsf[2][q]; D += rsf[3][q]; }
        d_part[blockIdx.x] = make_float4(A, Bv, C, D);
        __threadfence();
        unsigned prev = atomicAdd(&d_cnt, 1u);
        is_last_sh = (prev == NBLK - 1) ? 1u : 0u;
    }
    __syncthreads();

    // --- last block finalizes; 256 partials, one float4 per thread.
    // tid = batch*SPB + strip, so warp wwp holds exactly batch wwp's 32 strips.
    if (is_last_sh) {
        __shared__ double dsh[8];
        __shared__ float bsh[8];
        float4 f = __ldcg(&d_part[tid]);
        float a = f.x, bv = f.y, c = f.z, bd = f.w;
        #pragma unroll
        for (int o = 16; o; o >>= 1) {
            a  += __shfl_down_sync(0xffffffffu, a,  o);
            bv += __shfl_down_sync(0xffffffffu, bv, o);
            c  += __shfl_down_sync(0xffffffffu, c,  o);
            bd += __shfl_down_sync(0xffffffffu, bd, o);
        }
        if (lane == 0) {
            dsh[wwp] = 1.0 - (2.0 * (double)a + 1e-6) / ((double)bv + (double)c + 1e-6);
            bsh[wwp] = bd;
        }
        __syncthreads();

        if (tid == 0) {
            double d = 0.0, bbv = 0.0;
            #pragma unroll
            for (int q = 0; q < 8; q++) { d += dsh[q]; bbv += (double)bsh[q]; }
            out[0] = (float)(d * (1.0 / (double)Bn) + bbv * (1.0 / (double)NPIX));
            d_cnt = 0;   // reset for next graph replay (deterministic)
        }
    }
}

extern "C" void kernel_launch(void* const* d_in, const int* in_sizes, int n_in,
                              void* d_out, int out_size) {
    const float* pred   = (const float*)d_in[0];
    const float* target = (const float*)d_in[1];
    const int*   flg    = (const int*)d_in[2];
    float* out = (float*)d_out;

    fused_kernel<<<NBLK, 256>>>(pred, target, flg, out);
}

// round 14
// speedup vs baseline: 1.4597x; 1.0239x over previous
#include <cuda_runtime.h>
#include <math.h>

#define Bn 8
#define Hn 256
#define Wn 256
#define NPIX (Bn*Hn*Wn)       // 524288
#define INF_F 1e10f
#define RW 3                  // window radius; accept bound (RW+1)^2 = 16
#define RW_BOUND 16
#define SR 8                  // rows per thread
#define BSR 16                // rows per block (2 half-strips)
#define MR (SR + 2*RW)        // 14 g-rows per thread
#define MRT (BSR + 2*RW)      // 22 mask rows per block
#define SPB (Hn/BSR)          // 16 strips per batch
#define NBLK (Bn * SPB)       // 128 blocks
#define NT 512

// Packed per-block partials {spt, sp2, st, bnd}; disjoint coverage -> deterministic
__device__ float4 d_part[NBLK];
__device__ unsigned d_cnt = 0;   // completion counter (reset by last block)

// Unclamped window distance from offset-0 (bit 15) to nearest set bit.
// clz(0)=32 -> d=32 -> d^2=1024 (fits halfword; triggers fallback if min).
__device__ __forceinline__ unsigned win_dist(unsigned v) {
    int dl = __clz(v << 16);             // offset -d -> bit 31-d
    int dr = __clz(__brev(v >> 15));     // offset +d -> bit d -> reversed
    return (unsigned)min(dl, dr);
}

// Exact global fallback (bitwise-matches reference min-plus; never taken for
// benign inputs, preserves worst-case exactness).
__device__ __noinline__ float fb_min(const float* __restrict__ timg,
                                     int i, int w, bool want_one) {
    float m = 3.0e38f;
    for (int j = 0; j < Hn; j++) {
        int best = 1 << 20;
        for (int c = 0; c < Wn; c++) {
            float tv = timg[j * Wn + c];
            bool hit = want_one ? (tv > 0.5f) : (tv <= 0.5f);
            if (hit) best = min(best, abs(w - c));
        }
        float g = (best < Wn) ? (float)(best * best) : INF_F;
        float dj = (float)(i - j);
        m = fminf(m, fmaf(dj, dj, g));
    }
    return m;
}

__global__ void __launch_bounds__(NT) fused_kernel(
        const float* __restrict__ pred,
        const float* __restrict__ target,
        const int* __restrict__ flg,
        float* __restrict__ out) {
    __shared__ unsigned mskT[10][24];    // [seg -1..8][mask row 0..21], stride 24
    __shared__ float sq[64];             // sqrt LUT (exact sqrtf values)
    __shared__ float rsf[4][16];
    __shared__ unsigned is_last_sh;

    int tid  = threadIdx.x;
    int lane = tid & 31, wwp = tid >> 5;     // 16 warps
    int b      = blockIdx.x >> 4;            // batch
    int i0_blk = (blockIdx.x & 15) * BSR;    // block strip start row
    int j0_blk = i0_blk - RW;
    int half = tid >> 8;                     // 0 or 1: half-strip
    int w    = tid & 255;                    // column
    int i0   = i0_blk + half * SR;           // this thread's first output row
    int j0   = i0 - RW;
    const float* timg = target + b * (Hn * Wn);
    int fl = flg[0];

    // ---- pred loads FIRST: 8 independent LDGs in flight (max MLP)
    const float* prow = pred + (b * Hn + i0) * Wn + w;
    float pv[SR];
    #pragma unroll
    for (int k = 0; k < SR; k++)
        pv[k] = prow[k * Wn];

    // init: sqrt LUT + guard segments (global seg -1 and 8, all 22 rows)
    if (tid < 64) {
        sq[tid] = sqrtf((float)tid);
    } else if (tid < 64 + 2 * MRT) {
        int q = tid - 64;
        mskT[(q & 1) * 9][q >> 1] = 0u;
    }

    bool edge = (i0_blk == 0) || (i0_blk + BSR + RW > Hn);  // strips 0 and 15

    // --- target bitmasks: 22 rows over 16 warps; FFMA packing (t is 0/1 exact).
    // Lane covers cols 8l..8l+7; 4-lane groups merge into one 32-col segment.
    #pragma unroll
    for (int rr = 0; rr < 2; rr++) {
        int r = wwp + rr * 16;
        int j = j0_blk + r;
        bool okr = (rr == 0 || wwp < MRT - 16) &&
                   (!edge || (unsigned)j < (unsigned)Hn);
        if (okr) {
            const float4* tp = (const float4*)(timg + j * Wn) + lane * 2;
            float4 a = tp[0], c = tp[1];
            float s = a.x;
            s = fmaf(a.y,   2.f, s); s = fmaf(a.z,   4.f, s); s = fmaf(a.w,   8.f, s);
            s = fmaf(c.x,  16.f, s); s = fmaf(c.y,  32.f, s); s = fmaf(c.z,  64.f, s);
            s = fmaf(c.w, 128.f, s);
            unsigned v = ((unsigned)(int)s) << ((lane & 3) * 8);
            v |= __shfl_down_sync(0xffffffffu, v, 1, 4);
            v |= __shfl_down_sync(0xffffffffu, v, 2, 4);
            if ((lane & 3) == 0) mskT[(lane >> 2) + 1][r] = v;
        }
    }
    __syncthreads();

    // --- per-column row distances, packed dx^2 | dy^2<<16 (registers).
    int ww = w >> 5, bb = w & 31;
    int sh = (bb + 17) & 31;                 // uniform funnel shift amount
    bool hiSel = (bb >= 15);
    unsigned vmA = __funnelshift_r((ww >= 1) ? 0xffffffffu : 0u, 0xffffffffu, sh);
    unsigned vmB = __funnelshift_r(0xffffffffu, (ww <= 6) ? 0xffffffffu : 0u, sh);
    unsigned vm  = hiSel ? vmB : vmA;        // loop-invariant valid-column mask

    // segs ww-1, ww, ww+1 at +0,+24,+48; this thread's rows start at half*8
    const unsigned* bp = &mskT[ww][0] + half * SR;
    unsigned g[MR];
    if (!edge) {
        #pragma unroll
        for (int r = 0; r < MR; r++) {
            unsigned lo = bp[r], mw = bp[24 + r], hi = bp[48 + r];
            unsigned va = __funnelshift_r(lo, mw, sh);
            unsigned vb = __funnelshift_r(mw, hi, sh);
            unsigned v  = hiSel ? vb : va;
            unsigned center = (v >> 15) & 1u;
            unsigned selv = center ? ((~v) & vm) : v;
            unsigned d  = win_dist(selv);
            unsigned d2 = d * d;
            g[r] = center ? (d2 << 16) : d2;
        }
    } else {
        #pragma unroll
        for (int r = 0; r < MR; r++) {
            int j = j0 + r;
            if ((unsigned)j < (unsigned)Hn) {
                unsigned lo = bp[r], mw = bp[24 + r], hi = bp[48 + r];
                unsigned va = __funnelshift_r(lo, mw, sh);
                unsigned vb = __funnelshift_r(mw, hi, sh);
                unsigned v  = hiSel ? vb : va;
                unsigned center = (v >> 15) & 1u;
                unsigned selv = center ? ((~v) & vm) : v;
                unsigned d  = win_dist(selv);
                unsigned d2 = d * d;
                g[r] = center ? (d2 << 16) : d2;
            } else {
                g[r] = 49u | (49u << 16);    // >= 49: never accepted
            }
        }
    }

    // --- windowed column pass; min(mo,mi)==0 so s=mo+mi drives sqrt + bad test
    int mo[SR], mi[SR], s_[SR], smax = 0;
    #pragma unroll
    for (int k = 0; k < SR; k++) {
        unsigned m = g[k] + 0x00090009u;            // q = 9
        m = __vminu2(m, g[k + 1] + 0x00040004u);    // q = 4
        m = __vminu2(m, g[k + 2] + 0x00010001u);    // q = 1
        m = __vminu2(m, g[k + 3]);                  // q = 0 (center)
        m = __vminu2(m, g[k + 4] + 0x00010001u);
        m = __vminu2(m, g[k + 5] + 0x00040004u);
        m = __vminu2(m, g[k + 6] + 0x00090009u);
        mo[k] = (int)(m & 0xffffu);
        mi[k] = (int)(m >> 16);
        s_[k] = mo[k] + mi[k];
        smax = max(smax, s_[k]);
    }

    float dist[SR];
    #pragma unroll
    for (int k = 0; k < SR; k++)
        dist[k] = sq[min(s_[k], 63)];

    if (smax > RW_BOUND) {   // window min <= 16 is provably exact; rare rescue
        #pragma unroll
        for (int k = 0; k < SR; k++) {
            float fmo = (mo[k] <= RW_BOUND) ? (float)mo[k] : fb_min(timg, i0 + k, w, true);
            float fmi = (mi[k] <= RW_BOUND) ? (float)mi[k] : fb_min(timg, i0 + k, w, false);
            dist[k] = sqrtf(fmo) + sqrtf(fmi);
        }
    }

    // --- dice + boundary accumulation (fp32); tb == (mo == 0)
    float spt = 0.f, sp2 = 0.f, stt = 0.f, bsum = 0.f;
    #pragma unroll
    for (int k = 0; k < SR; k++) {
        float p = pv[k];
        if (fl) {   // sigmoid(x) = 0.5 + 0.5*tanh(x/2)
            float th;
            asm("tanh.approx.f32 %0, %1;" : "=f"(th) : "f"(p * 0.5f));
            p = fmaf(th, 0.5f, 0.5f);
        }
        float tb = (mo[k] == 0) ? 1.0f : 0.0f;
        spt  += p * tb;
        sp2  += p * p;
        stt  += tb;
        bsum += p * dist[k];
    }

    // --- block reduction (fp32), 16 warps
    #pragma unroll
    for (int o = 16; o; o >>= 1) {
        spt  += __shfl_down_sync(0xffffffffu, spt,  o);
        sp2  += __shfl_down_sync(0xffffffffu, sp2,  o);
        stt  += __shfl_down_sync(0xffffffffu, stt,  o);
        bsum += __shfl_down_sync(0xffffffffu, bsum, o);
    }
    if (lane == 0) { rsf[0][wwp] = spt; rsf[1][wwp] = sp2; rsf[2][wwp] = stt; rsf[3][wwp] = bsum; }
    __syncthreads();

    if (tid == 0) {
        float A = 0.f, Bv = 0.f, C = 0.f, D = 0.f;
        #pragma unroll
        for (int q = 0; q < 16; q++) { A += rsf[0][q]; Bv += rsf[1][q]; C += rsf[2][q]; D += rsf[3][q]; }
        d_part[blockIdx.x] = make_float4(A, Bv, C, D);
        __threadfence();
        unsigned prev = atomicAdd(&d_cnt, 1u);
        is_last_sh = (prev == NBLK - 1) ? 1u : 0u;
    }
    __syncthreads();

    // --- last block finalizes; 128 partials over 4 warps, 16-lane batch groups
    if (is_last_sh) {
        __shared__ double dsh[8];
        __shared__ float bsh[4];
        if (tid < NBLK) {
            float4 f = __ldcg(&d_part[tid]);
            float a = f.x, bv = f.y, c = f.z, bd = f.w;
            // per-batch dice sums: 16 consecutive blocks = one batch
            #pragma unroll
            for (int o = 8; o; o >>= 1) {
                a  += __shfl_down_sync(0xffffffffu, a,  o, 16);
                bv += __shfl_down_sync(0xffffffffu, bv, o, 16);
                c  += __shfl_down_sync(0xffffffffu, c,  o, 16);
            }
            if ((lane & 15) == 0)
                dsh[wwp * 2 + (lane >> 4)] =
                    1.0 - (2.0 * (double)a + 1e-6) / ((double)bv + (double)c + 1e-6);
            // boundary: full-warp sum
            #pragma unroll
            for (int o = 16; o; o >>= 1)
                bd += __shfl_down_sync(0xffffffffu, bd, o);
            if (lane == 0) bsh[wwp] = bd;
        }
        __syncthreads();

        if (tid == 0) {
            double d = 0.0, bbv = 0.0;
            #pragma unroll
            for (int q = 0; q < 8; q++) d += dsh[q];
            #pragma unroll
            for (int q = 0; q < 4; q++) bbv += (double)bsh[q];
            out[0] = (float)(d * (1.0 / (double)Bn) + bbv * (1.0 / (double)NPIX));
            d_cnt = 0;   // reset for next graph replay (deterministic)
        }
    }
}

extern "C" void kernel_launch(void* const* d_in, const int* in_sizes, int n_in,
                              void* d_out, int out_size) {
    const float* pred   = (const float*)d_in[0];
    const float* target = (const float*)d_in[1];
    const int*   flg    = (const int*)d_in[2];
    float* out = (float*)d_out;

    fused_kernel<<<NBLK, NT>>>(pred, target, flg, out);
}